// round 9
// baseline (speedup 1.0000x reference)
#include <cuda_runtime.h>
#include <cuda_fp16.h>
#include <cstdint>
#include <cstddef>

#define BB   4
#define CC   256
#define NN   4096
#define GG   32
#define CPG  8
#define EPSV 1e-5f

#define TBM 128
#define TBK 32            // halves per k-chunk (2 x k16 MMA steps)
#define SKH 40            // smem row stride in halves (80B) -> LDSM conflict-free
#define STAGES 4
#define TILE_A (TBM * SKH * 2)       // 10240 B
#define NMT 16                        // scores n-tiles (BN=256)

// ---------------- scratch (device globals) ----------------------------------
__device__ __half g_wqkh[512 * CC];              // rows 0-255: wq/4, 256-511: wk/4
__device__ __half g_wvh [CC * CC];
__device__ __half g_woh [CC * CC];
__device__ float  g_bqk [512];                   // bq/4, bk/4
__device__ __half g_hn  [(size_t)BB * NN * CC];  // [b][n][c]
__device__ __half g_qkh [(size_t)BB * NN * 512]; // [b][n][512]
__device__ __half g_v   [(size_t)BB * CC * NN];  // [b][c][n]
__device__ __half g_eS  [(size_t)BB * NN * NN];  // expS [b][nq][nk]
__device__ __half g_at  [(size_t)BB * NN * CC];  // attn [b][nq][c]
__device__ float  g_mean[BB * GG];
__device__ float  g_rstd[BB * GG];
__device__ float  g_ps  [(size_t)BB * NMT * NN]; // partial row sums
__device__ float  g_invL[BB * NN];

// ---------------- helpers ----------------------------------------------------
__device__ __forceinline__ void mma_f16(float* c, const uint32_t* a, uint32_t b0, uint32_t b1)
{
    asm volatile(
        "mma.sync.aligned.m16n8k16.row.col.f32.f16.f16.f32 "
        "{%0,%1,%2,%3},{%4,%5,%6,%7},{%8,%9},{%0,%1,%2,%3};\n"
        : "+f"(c[0]), "+f"(c[1]), "+f"(c[2]), "+f"(c[3])
        : "r"(a[0]), "r"(a[1]), "r"(a[2]), "r"(a[3]), "r"(b0), "r"(b1));
}
__device__ __forceinline__ void ldsm_x4(uint32_t* r, uint32_t addr)
{
    asm volatile("ldmatrix.sync.aligned.m8n8.x4.shared.b16 {%0,%1,%2,%3}, [%4];"
                 : "=r"(r[0]), "=r"(r[1]), "=r"(r[2]), "=r"(r[3]) : "r"(addr));
}
__device__ __forceinline__ void cp_async16(void* smem_dst, const void* gptr)
{
    uint32_t s = (uint32_t)__cvta_generic_to_shared(smem_dst);
    asm volatile("cp.async.cg.shared.global [%0], [%1], 16;\n" :: "r"(s), "l"(gptr));
}
__device__ __forceinline__ void cp_commit() { asm volatile("cp.async.commit_group;\n"); }
template <int Nw>
__device__ __forceinline__ void cp_wait() { asm volatile("cp.async.wait_group %0;\n" :: "n"(Nw)); }

// ---------------- prep: convert weights to half ------------------------------
__global__ void prep_weights(const float* __restrict__ wq, const float* __restrict__ wk,
                             const float* __restrict__ wv, const float* __restrict__ wo,
                             const float* __restrict__ bq, const float* __restrict__ bk)
{
    int i = blockIdx.x * blockDim.x + threadIdx.x;
    if (i < 131072) {                         // wqk (512x256), scaled 1/4
        int r = i >> 8;
        float v = (r < 256) ? wq[i] : wk[i - 65536];
        g_wqkh[i] = __float2half(v * 0.25f);
    } else if (i < 196608) {
        g_wvh[i - 131072] = __float2half(wv[i - 131072]);
    } else if (i < 262144) {
        g_woh[i - 196608] = __float2half(wo[i - 196608]);
    } else if (i < 262656) {
        int j = i - 262144;
        g_bqk[j] = ((j < 256) ? bq[j] : bk[j - 256]) * 0.25f;
    }
}

// ---------------- groupnorm --------------------------------------------------
__global__ void gn_stats(const float* __restrict__ x)
{
    int bg = blockIdx.x;
    const float* xs = x + (size_t)bg * (CPG * NN);
    float s = 0.f, s2 = 0.f;
    for (int i = threadIdx.x; i < CPG * NN; i += 256) {
        float v = xs[i];
        s += v; s2 += v * v;
    }
    __shared__ float rs[512];
    rs[threadIdx.x] = s; rs[256 + threadIdx.x] = s2;
    __syncthreads();
    for (int off = 128; off > 0; off >>= 1) {
        if (threadIdx.x < off) {
            rs[threadIdx.x]       += rs[threadIdx.x + off];
            rs[256 + threadIdx.x] += rs[256 + threadIdx.x + off];
        }
        __syncthreads();
    }
    if (threadIdx.x == 0) {
        float mean = rs[0] * (1.f / (CPG * NN));
        float var  = rs[256] * (1.f / (CPG * NN)) - mean * mean;
        g_mean[bg] = mean;
        g_rstd[bg] = rsqrtf(var + EPSV);
    }
}

// x[b][c][n] -> hn[b][n][c] (half). block (32,8), grid (NN/32, CC/32, BB)
__global__ void gn_transpose(const float* __restrict__ x,
                             const float* __restrict__ gamma, const float* __restrict__ beta)
{
    __shared__ float tile[32][33];
    int b = blockIdx.z;
    int n0 = blockIdx.x * 32, c0 = blockIdx.y * 32;
    int tx = threadIdx.x, ty = threadIdx.y;
    const float* xb = x + (size_t)b * CC * NN;
#pragma unroll
    for (int j = 0; j < 4; j++) {
        int c = c0 + ty + j * 8;
        float mean = g_mean[b * GG + (c >> 3)];
        float rstd = g_rstd[b * GG + (c >> 3)];
        float ga = gamma[c] * rstd;
        float be = beta[c] - mean * ga;
        tile[ty + j * 8][tx] = xb[(size_t)c * NN + n0 + tx] * ga + be;
    }
    __syncthreads();
    __half* hb = g_hn + (size_t)b * NN * CC;
#pragma unroll
    for (int j = 0; j < 4; j++) {
        int n = n0 + ty + j * 8;
        hb[(size_t)n * CC + c0 + tx] = __float2half(tile[tx][ty + j * 8]);
    }
}

// ---------------- fp16 TC GEMM, templated block width -------------------------
// BN=256: 8 warps as 2x4 of 64x64 warp tiles, 1 CTA/SM, ~200 regs.
// BN=128: 8 warps as 2x4 of 64x32 warp tiles, 2 CTAs/SM.
// C[m][n] = sum_k A[m][k] * B[n][k]
// mode 0: half out, + bias_row[m] + bias_col[n]
// mode 1: half out = exp(acc); per-block row sums -> psum
// mode 2: half out = acc * rowscale[b*M + m]
// mode 3: fp32 out = acc + bias_row[m] + residual
template <int BN>
__global__ void __launch_bounds__(256, (BN == 128) ? 2 : 1)
hgemm(const __half* __restrict__ A, int ldA, size_t sA,
      const __half* __restrict__ B, int ldB, size_t sB,
      void* __restrict__ Cv, int ldC, size_t sC,
      int M, int K,
      const float* __restrict__ bias_row, const float* __restrict__ bias_col,
      const float* __restrict__ residual, const float* __restrict__ rowscale,
      float* __restrict__ psum, int mode)
{
    constexpr int WN   = BN / 4;      // warp n-width
    constexpr int NP   = BN / 64;     // B ldsm.x4 groups per k-step
    constexpr int NNT  = BN / 32;     // n8 tiles per warp
    constexpr int TILE_Bn  = BN * SKH * 2;
    constexpr int STAGE_B  = TILE_A + TILE_Bn;

    const int b  = blockIdx.z;
    const int m0 = blockIdx.y * TBM;
    const int n0 = blockIdx.x * BN;

    extern __shared__ char smem[];
    __shared__ float cs[512];

    const int tid  = threadIdx.x;
    const int lane = tid & 31;
    const int wid  = tid >> 5;
    const int wm   = wid >> 2;
    const int wn   = wid & 3;
    const int g    = lane >> 2;
    const int th4  = lane & 3;
    const int mi   = lane >> 3;
    const int ri   = lane & 7;

    const __half* Ap = A + (size_t)b * sA + (size_t)m0 * ldA;
    const __half* Bp = B + (size_t)b * sB + (size_t)n0 * ldB;

    const uint32_t su = (uint32_t)__cvta_generic_to_shared(smem);

    float acc[4][NNT][4];
#pragma unroll
    for (int i = 0; i < 4; i++)
#pragma unroll
        for (int j = 0; j < NNT; j++)
#pragma unroll
            for (int r = 0; r < 4; r++) acc[i][j][r] = 0.f;

    const int T = K / TBK;
    const int crow = tid >> 2;
    const int c4   = tid & 3;

    auto load_tile = [&](int st, int t) {
        char* sa = smem + st * STAGE_B;
        char* sb = sa + TILE_A;
        const __half* Ag = Ap + (size_t)t * TBK;
        const __half* Bg = Bp + (size_t)t * TBK;
#pragma unroll
        for (int j = 0; j < 2; j++) {
            int row = crow + j * 64;
            cp_async16(sa + row * (SKH * 2) + c4 * 16, Ag + (size_t)row * ldA + c4 * 8);
        }
#pragma unroll
        for (int j = 0; j < NP; j++) {
            int row = crow + j * 64;
            cp_async16(sb + row * (SKH * 2) + c4 * 16, Bg + (size_t)row * ldB + c4 * 8);
        }
    };

#pragma unroll
    for (int t = 0; t < STAGES - 1; t++) {
        if (t < T) load_tile(t, t);
        cp_commit();
    }

    for (int t = 0; t < T; t++) {
        cp_wait<STAGES - 2>();
        __syncthreads();

        int tl = t + STAGES - 1;
        if (tl < T) load_tile(tl % STAGES, tl);
        cp_commit();

        const int slot = t % STAGES;
        const uint32_t a_base = su + slot * STAGE_B;
        const uint32_t b_base = a_base + TILE_A;

#pragma unroll
        for (int kk = 0; kk < TBK; kk += 16) {
            uint32_t av[4][4];
#pragma unroll
            for (int mt = 0; mt < 4; mt++) {
                int row = wm * 64 + mt * 16 + ((mi & 1) << 3) + ri;
                int col = kk + ((mi & 2) << 2);
                ldsm_x4(av[mt], a_base + (row * SKH + col) * 2);
            }
            uint32_t bv[NP][4];
#pragma unroll
            for (int p = 0; p < NP; p++) {
                int row = wn * WN + p * 16 + ((mi >> 1) << 3) + ri;
                int col = kk + ((mi & 1) << 3);
                ldsm_x4(bv[p], b_base + (row * SKH + col) * 2);
            }
#pragma unroll
            for (int mt = 0; mt < 4; mt++)
#pragma unroll
                for (int nt = 0; nt < NNT; nt++)
                    mma_f16(acc[mt][nt], av[mt], bv[nt >> 1][(nt & 1) * 2], bv[nt >> 1][(nt & 1) * 2 + 1]);
        }
    }

    // ---------------- epilogues ----------------
    if (mode == 1) {
        __half* C = (__half*)Cv + (size_t)b * sC;
        float rsum[8];
#pragma unroll
        for (int i = 0; i < 8; i++) rsum[i] = 0.f;
#pragma unroll
        for (int mt = 0; mt < 4; mt++) {
#pragma unroll
            for (int nt = 0; nt < NNT; nt++) {
                int col = n0 + wn * WN + nt * 8 + 2 * th4;
#pragma unroll
                for (int h = 0; h < 2; h++) {
                    int row = m0 + wm * 64 + mt * 16 + g + 8 * h;
                    float e0 = __expf(acc[mt][nt][2 * h]);
                    float e1 = __expf(acc[mt][nt][2 * h + 1]);
                    rsum[mt * 2 + h] += e0 + e1;
                    *(__half2*)(C + (size_t)row * ldC + col) = __floats2half2_rn(e0, e1);
                }
            }
        }
#pragma unroll
        for (int i = 0; i < 8; i++) {
            rsum[i] += __shfl_xor_sync(0xffffffffu, rsum[i], 1);
            rsum[i] += __shfl_xor_sync(0xffffffffu, rsum[i], 2);
        }
        if (th4 == 0) {
#pragma unroll
            for (int mt = 0; mt < 4; mt++)
#pragma unroll
                for (int h = 0; h < 2; h++)
                    cs[wn * 128 + wm * 64 + mt * 16 + g + 8 * h] = rsum[mt * 2 + h];
        }
        __syncthreads();
        if (tid < 128) {
            float tot = cs[tid] + cs[128 + tid] + cs[256 + tid] + cs[384 + tid];
            psum[((size_t)b * (NN / BN) + blockIdx.x) * M + m0 + tid] = tot;
        }
        return;
    }

    if (mode == 3) {
        float* C = (float*)Cv + (size_t)b * sC;
        const float* R = residual + (size_t)b * sC;
#pragma unroll
        for (int mt = 0; mt < 4; mt++) {
#pragma unroll
            for (int nt = 0; nt < NNT; nt++) {
                int col = n0 + wn * WN + nt * 8 + 2 * th4;
#pragma unroll
                for (int h = 0; h < 2; h++) {
                    int row = m0 + wm * 64 + mt * 16 + g + 8 * h;
                    float br = bias_row[row];
                    float2 rv = *(const float2*)(R + (size_t)row * ldC + col);
                    float2 o;
                    o.x = acc[mt][nt][2 * h]     + br + rv.x;
                    o.y = acc[mt][nt][2 * h + 1] + br + rv.y;
                    *(float2*)(C + (size_t)row * ldC + col) = o;
                }
            }
        }
        return;
    }

    __half* C = (__half*)Cv + (size_t)b * sC;
    const float* rsc = (mode == 2) ? (rowscale + (size_t)b * M) : nullptr;
#pragma unroll
    for (int mt = 0; mt < 4; mt++) {
#pragma unroll
        for (int nt = 0; nt < NNT; nt++) {
            int col = n0 + wn * WN + nt * 8 + 2 * th4;
            float bc0 = bias_col ? bias_col[col]     : 0.f;
            float bc1 = bias_col ? bias_col[col + 1] : 0.f;
#pragma unroll
            for (int h = 0; h < 2; h++) {
                int row = m0 + wm * 64 + mt * 16 + g + 8 * h;
                float o0 = acc[mt][nt][2 * h];
                float o1 = acc[mt][nt][2 * h + 1];
                if (mode == 2) {
                    float sc = rsc[row];
                    o0 *= sc; o1 *= sc;
                } else {
                    float br = bias_row ? bias_row[row] : 0.f;
                    o0 += br + bc0; o1 += br + bc1;
                }
                *(__half2*)(C + (size_t)row * ldC + col) = __floats2half2_rn(o0, o1);
            }
        }
    }
}

// ---------------- invL: reduce partial row sums ------------------------------
__global__ void invl_reduce()
{
    int idx = blockIdx.x * blockDim.x + threadIdx.x;   // b*NN + nq
    int b = idx >> 12;
    int n = idx & (NN - 1);
    float s = 0.f;
#pragma unroll
    for (int t = 0; t < NMT; t++)
        s += g_ps[((size_t)b * NMT + t) * NN + n];
    g_invL[idx] = 1.f / s;
}

// ---------------- launch -----------------------------------------------------
extern "C" void kernel_launch(void* const* d_in, const int* in_sizes, int n_in,
                              void* d_out, int out_size)
{
    const float* x     = (const float*)d_in[0];
    const float* gamma = (const float*)d_in[1];
    const float* beta  = (const float*)d_in[2];
    const float* wq    = (const float*)d_in[3];
    const float* bq    = (const float*)d_in[4];
    const float* wk    = (const float*)d_in[5];
    const float* bk    = (const float*)d_in[6];
    const float* wv    = (const float*)d_in[7];
    const float* bv    = (const float*)d_in[8];
    const float* wo    = (const float*)d_in[9];
    const float* bo    = (const float*)d_in[10];
    float* out = (float*)d_out;

    __half *wqkh, *wvh, *woh, *hn, *qkh, *v, *eS, *at;
    float *bqk, *ps, *invL;
    cudaGetSymbolAddress((void**)&wqkh, g_wqkh);
    cudaGetSymbolAddress((void**)&wvh,  g_wvh);
    cudaGetSymbolAddress((void**)&woh,  g_woh);
    cudaGetSymbolAddress((void**)&bqk,  g_bqk);
    cudaGetSymbolAddress((void**)&hn,   g_hn);
    cudaGetSymbolAddress((void**)&qkh,  g_qkh);
    cudaGetSymbolAddress((void**)&v,    g_v);
    cudaGetSymbolAddress((void**)&eS,   g_eS);
    cudaGetSymbolAddress((void**)&at,   g_at);
    cudaGetSymbolAddress((void**)&ps,   g_ps);
    cudaGetSymbolAddress((void**)&invL, g_invL);

    constexpr int SMEM_128 = STAGES * (TILE_A + 128 * SKH * 2);
    constexpr int SMEM_256 = STAGES * (TILE_A + 256 * SKH * 2);

    static bool attr_set = false;
    if (!attr_set) {
        cudaFuncSetAttribute(hgemm<128>, cudaFuncAttributeMaxDynamicSharedMemorySize, SMEM_128);
        cudaFuncSetAttribute(hgemm<256>, cudaFuncAttributeMaxDynamicSharedMemorySize, SMEM_256);
        attr_set = true;
    }

    prep_weights<<<(262656 + 255) / 256, 256>>>(wq, wk, wv, wo, bq, bk);
    gn_stats<<<BB * GG, 256>>>(x);
    gn_transpose<<<dim3(NN / 32, CC / 32, BB), dim3(32, 8)>>>(x, gamma, beta);

    // qk[n][512] = hn[n][c] x wqk[d][c]^T + bqk   (BN=256: grid 2x32x4)
    hgemm<256><<<dim3(2, NN / TBM, BB), 256, SMEM_256>>>(
        hn, CC, (size_t)NN * CC, wqkh, CC, 0,
        qkh, 512, (size_t)NN * 512, NN, CC,
        nullptr, bqk, nullptr, nullptr, nullptr, 0);

    // v[c][n] = wv[c][k] x hn[n][k]^T + bv[c]   (BN=256: grid 16x2x4)
    hgemm<256><<<dim3(NN / 256, CC / TBM, BB), 256, SMEM_256>>>(
        wvh, CC, 0, hn, CC, (size_t)NN * CC,
        v, NN, (size_t)CC * NN, CC, CC,
        bv, nullptr, nullptr, nullptr, nullptr, 0);

    // expS[nq][nk] = exp(q . k), per-block row sums   (BN=256: grid 16x32x4)
    hgemm<256><<<dim3(NN / 256, NN / TBM, BB), 256, SMEM_256>>>(
        qkh, 512, (size_t)NN * 512, qkh + 256, 512, (size_t)NN * 512,
        eS, NN, (size_t)NN * NN, NN, CC,
        nullptr, nullptr, nullptr, nullptr, ps, 1);

    invl_reduce<<<BB * NN / 256, 256>>>();

    // attn[nq][c] = (expS[nq][nk] x v[c][nk]^T) * invL[nq]  (BN=128: grid 2x32x4)
    hgemm<128><<<dim3(CC / 128, NN / TBM, BB), 256, SMEM_128>>>(
        eS, NN, (size_t)NN * NN, v, NN, (size_t)CC * NN,
        at, CC, (size_t)NN * CC, NN, NN,
        nullptr, nullptr, nullptr, invL, nullptr, 2);

    // out[c][n] = wo[c][k] x attn[n][k]^T + bo[c] + x[c][n]  (fp32, BN=256)
    hgemm<256><<<dim3(NN / 256, CC / TBM, BB), 256, SMEM_256>>>(
        woh, CC, 0, at, CC, (size_t)NN * CC,
        out, NN, (size_t)CC * NN, CC, CC,
        bo, nullptr, x, nullptr, nullptr, 3);
}

// round 10
// speedup vs baseline: 1.0559x; 1.0559x over previous
#include <cuda_runtime.h>
#include <cuda_fp16.h>
#include <cstdint>
#include <cstddef>

#define BB   4
#define CC   256
#define NN   4096
#define GG   32
#define CPG  8
#define EPSV 1e-5f

#define TBM 128
#define TBN 128
#define TBK 32            // halves per k-chunk (2 x k16 MMA steps)
#define SKH 40            // K-major smem row stride in halves (80B)
#define SKB 136           // BTRANS smem row stride in halves (272B)
#define STAGES 4
#define TILE_A (TBM * SKH * 2)            // 10240 B
#define TILE_B0 (TBN * SKH * 2)           // 10240 B (B K-major)
#define TILE_B1 (TBK * SKB * 2)           // 8704 B  (B k-row-major, trans)
#define NMT (NN / TBN)                    // 32

// ---------------- scratch (device globals) ----------------------------------
__device__ __half g_wqkvh[768 * CC];             // rows 0-255 wq/4, 256-511 wk/4, 512-767 wv
__device__ __half g_woh [CC * CC];
__device__ float  g_bqkv[768];                   // bq/4, bk/4, bv
__device__ __half g_hn  [(size_t)BB * NN * CC];  // [b][n][c]
__device__ __half g_qkv [(size_t)BB * NN * 768]; // [b][n][768]
__device__ __half g_eS  [(size_t)BB * NN * NN];  // expS [b][nq][nk]
__device__ __half g_at  [(size_t)BB * NN * CC];  // attn [b][nq][c]
__device__ float  g_mean[BB * GG];
__device__ float  g_rstd[BB * GG];
__device__ float  g_ps  [(size_t)BB * NMT * NN]; // partial row sums
__device__ float  g_invL[BB * NN];

// ---------------- helpers ----------------------------------------------------
__device__ __forceinline__ void mma_f16(float* c, const uint32_t* a, uint32_t b0, uint32_t b1)
{
    asm volatile(
        "mma.sync.aligned.m16n8k16.row.col.f32.f16.f16.f32 "
        "{%0,%1,%2,%3},{%4,%5,%6,%7},{%8,%9},{%0,%1,%2,%3};\n"
        : "+f"(c[0]), "+f"(c[1]), "+f"(c[2]), "+f"(c[3])
        : "r"(a[0]), "r"(a[1]), "r"(a[2]), "r"(a[3]), "r"(b0), "r"(b1));
}
__device__ __forceinline__ void ldsm_x4(uint32_t* r, uint32_t addr)
{
    asm volatile("ldmatrix.sync.aligned.m8n8.x4.shared.b16 {%0,%1,%2,%3}, [%4];"
                 : "=r"(r[0]), "=r"(r[1]), "=r"(r[2]), "=r"(r[3]) : "r"(addr));
}
__device__ __forceinline__ void ldsm_x4_t(uint32_t* r, uint32_t addr)
{
    asm volatile("ldmatrix.sync.aligned.m8n8.x4.trans.shared.b16 {%0,%1,%2,%3}, [%4];"
                 : "=r"(r[0]), "=r"(r[1]), "=r"(r[2]), "=r"(r[3]) : "r"(addr));
}
__device__ __forceinline__ void cp_async16(void* smem_dst, const void* gptr)
{
    uint32_t s = (uint32_t)__cvta_generic_to_shared(smem_dst);
    asm volatile("cp.async.cg.shared.global [%0], [%1], 16;\n" :: "r"(s), "l"(gptr));
}
__device__ __forceinline__ void cp_commit() { asm volatile("cp.async.commit_group;\n"); }
template <int Nw>
__device__ __forceinline__ void cp_wait() { asm volatile("cp.async.wait_group %0;\n" :: "n"(Nw)); }

// ---------------- prep: pack + convert weights to half -----------------------
__global__ void prep_weights(const float* __restrict__ wq, const float* __restrict__ wk,
                             const float* __restrict__ wv, const float* __restrict__ wo,
                             const float* __restrict__ bq, const float* __restrict__ bk,
                             const float* __restrict__ bv)
{
    int i = blockIdx.x * blockDim.x + threadIdx.x;
    if (i < 196608) {                          // wqkv [768][256]
        int r = i >> 8;
        float v;
        if (r < 256)      v = wq[i] * 0.25f;
        else if (r < 512) v = wk[i - 65536] * 0.25f;
        else              v = wv[i - 131072];
        g_wqkvh[i] = __float2half(v);
    } else if (i < 262144) {
        g_woh[i - 196608] = __float2half(wo[i - 196608]);
    } else if (i < 262912) {
        int j = i - 262144;
        float v;
        if (j < 256)      v = bq[j] * 0.25f;
        else if (j < 512) v = bk[j - 256] * 0.25f;
        else              v = bv[j - 512];
        g_bqkv[j] = v;
    }
}

// ---------------- groupnorm --------------------------------------------------
__global__ void gn_stats(const float* __restrict__ x)
{
    int bg = blockIdx.x;
    const float* xs = x + (size_t)bg * (CPG * NN);
    float s = 0.f, s2 = 0.f;
    for (int i = threadIdx.x; i < CPG * NN; i += 256) {
        float v = xs[i];
        s += v; s2 += v * v;
    }
    __shared__ float rs[512];
    rs[threadIdx.x] = s; rs[256 + threadIdx.x] = s2;
    __syncthreads();
    for (int off = 128; off > 0; off >>= 1) {
        if (threadIdx.x < off) {
            rs[threadIdx.x]       += rs[threadIdx.x + off];
            rs[256 + threadIdx.x] += rs[256 + threadIdx.x + off];
        }
        __syncthreads();
    }
    if (threadIdx.x == 0) {
        float mean = rs[0] * (1.f / (CPG * NN));
        float var  = rs[256] * (1.f / (CPG * NN)) - mean * mean;
        g_mean[bg] = mean;
        g_rstd[bg] = rsqrtf(var + EPSV);
    }
}

// x[b][c][n] -> hn[b][n][c] (half). block (32,8), grid (NN/32, CC/32, BB)
__global__ void gn_transpose(const float* __restrict__ x,
                             const float* __restrict__ gamma, const float* __restrict__ beta)
{
    __shared__ float tile[32][33];
    int b = blockIdx.z;
    int n0 = blockIdx.x * 32, c0 = blockIdx.y * 32;
    int tx = threadIdx.x, ty = threadIdx.y;
    const float* xb = x + (size_t)b * CC * NN;
#pragma unroll
    for (int j = 0; j < 4; j++) {
        int c = c0 + ty + j * 8;
        float mean = g_mean[b * GG + (c >> 3)];
        float rstd = g_rstd[b * GG + (c >> 3)];
        float ga = gamma[c] * rstd;
        float be = beta[c] - mean * ga;
        tile[ty + j * 8][tx] = xb[(size_t)c * NN + n0 + tx] * ga + be;
    }
    __syncthreads();
    __half* hb = g_hn + (size_t)b * NN * CC;
#pragma unroll
    for (int j = 0; j < 4; j++) {
        int n = n0 + ty + j * 8;
        hb[(size_t)n * CC + c0 + tx] = __float2half(tile[tx][ty + j * 8]);
    }
}

// ---------------- fp16 TC GEMM (128x128, 2 CTA/SM, pipelined fragments) ------
// BTRANS=0: B stored [n][k] K-major.  BTRANS=1: B stored [k][n] (trans ldmatrix).
// C[m][n] = sum_k A[m][k] * B[k-ish]
// mode 0: half out, + bias_col[n]
// mode 1: half out = exp(acc); per-block row sums -> psum
// mode 2: half out = acc * rowscale[b*M + m]
// mode 3: fp32 out = acc + bias_row[m] + residual
template <int BTRANS>
__global__ void __launch_bounds__(256, 2)
hgemm(const __half* __restrict__ A, int ldA, size_t sA,
      const __half* __restrict__ B, int ldB, size_t sB,
      void* __restrict__ Cv, int ldC, size_t sC,
      int M, int K,
      const float* __restrict__ bias_row, const float* __restrict__ bias_col,
      const float* __restrict__ residual, const float* __restrict__ rowscale,
      float* __restrict__ psum, int mode)
{
    constexpr int TILE_Bx = BTRANS ? TILE_B1 : TILE_B0;
    constexpr int STAGE_B = TILE_A + TILE_Bx;

    const int b  = blockIdx.z;
    const int m0 = blockIdx.y * TBM;
    const int n0 = blockIdx.x * TBN;

    extern __shared__ char smem[];
    __shared__ float cs[512];

    const int tid  = threadIdx.x;
    const int lane = tid & 31;
    const int wid  = tid >> 5;
    const int wm   = wid >> 2;
    const int wn   = wid & 3;
    const int g    = lane >> 2;
    const int th4  = lane & 3;
    const int mi   = lane >> 3;
    const int ri   = lane & 7;

    const __half* Ap = A + (size_t)b * sA + (size_t)m0 * ldA;
    const __half* Bp = BTRANS ? (B + (size_t)b * sB + n0)
                              : (B + (size_t)b * sB + (size_t)n0 * ldB);

    const uint32_t su = (uint32_t)__cvta_generic_to_shared(smem);

    float acc[4][4][4];
#pragma unroll
    for (int i = 0; i < 4; i++)
#pragma unroll
        for (int j = 0; j < 4; j++)
#pragma unroll
            for (int r = 0; r < 4; r++) acc[i][j][r] = 0.f;

    const int T = K / TBK;
    const int crow = tid >> 2;        // 0..63
    const int c4   = tid & 3;

    auto load_tile = [&](int st, int t) {
        char* sa = smem + st * STAGE_B;
        char* sb = sa + TILE_A;
        const __half* Ag = Ap + (size_t)t * TBK;
#pragma unroll
        for (int j = 0; j < 2; j++) {
            int row = crow + j * 64;
            cp_async16(sa + row * (SKH * 2) + c4 * 16, Ag + (size_t)row * ldA + c4 * 8);
        }
        if (BTRANS) {
            const __half* Bg = Bp + (size_t)t * TBK * ldB;
            // [32 k-rows][128 n-cols]: 512 16B slots, 2 per thread
#pragma unroll
            for (int j = 0; j < 2; j++) {
                int slot = tid + j * 256;
                int row = slot >> 4, col = slot & 15;
                cp_async16(sb + row * (SKB * 2) + col * 16, Bg + (size_t)row * ldB + col * 8);
            }
        } else {
            const __half* Bg = Bp + (size_t)t * TBK;
#pragma unroll
            for (int j = 0; j < 2; j++) {
                int row = crow + j * 64;
                cp_async16(sb + row * (SKH * 2) + c4 * 16, Bg + (size_t)row * ldB + c4 * 8);
            }
        }
    };

#pragma unroll
    for (int t = 0; t < STAGES - 1; t++) {
        if (t < T) load_tile(t, t);
        cp_commit();
    }

    for (int t = 0; t < T; t++) {
        cp_wait<STAGES - 2>();
        __syncthreads();

        int tl = t + STAGES - 1;
        if (tl < T) load_tile(tl % STAGES, tl);
        cp_commit();

        const int slot = t % STAGES;
        const uint32_t a_base = su + slot * STAGE_B;
        const uint32_t b_base = a_base + TILE_A;

        uint32_t av[2][4][4], bv[2][2][4];
        // --- issue ALL fragment loads for both k16 steps first ---
#pragma unroll
        for (int ph = 0; ph < 2; ph++) {
            const int kk = ph * 16;
#pragma unroll
            for (int mt = 0; mt < 4; mt++) {
                int row = wm * 64 + mt * 16 + ((mi & 1) << 3) + ri;
                int col = kk + ((mi & 2) << 2);
                ldsm_x4(av[ph][mt], a_base + (row * SKH + col) * 2);
            }
            if (BTRANS) {
#pragma unroll
                for (int p = 0; p < 2; p++) {
                    int krow = kk + ((mi & 1) << 3) + ri;
                    int col  = wn * 32 + p * 16 + ((mi >> 1) << 3);
                    ldsm_x4_t(bv[ph][p], b_base + (krow * SKB + col) * 2);
                }
            } else {
#pragma unroll
                for (int p = 0; p < 2; p++) {
                    int row = wn * 32 + p * 16 + ((mi >> 1) << 3) + ri;
                    int col = kk + ((mi & 1) << 3);
                    ldsm_x4(bv[ph][p], b_base + (row * SKH + col) * 2);
                }
            }
        }
        // --- then all 32 MMAs ---
#pragma unroll
        for (int ph = 0; ph < 2; ph++)
#pragma unroll
            for (int mt = 0; mt < 4; mt++)
#pragma unroll
                for (int nt = 0; nt < 4; nt++)
                    mma_f16(acc[mt][nt], av[ph][mt],
                            bv[ph][nt >> 1][(nt & 1) * 2], bv[ph][nt >> 1][(nt & 1) * 2 + 1]);
    }

    // ---------------- epilogues ----------------
    if (mode == 1) {
        __half* C = (__half*)Cv + (size_t)b * sC;
        float rsum[8];
#pragma unroll
        for (int i = 0; i < 8; i++) rsum[i] = 0.f;
#pragma unroll
        for (int mt = 0; mt < 4; mt++) {
#pragma unroll
            for (int nt = 0; nt < 4; nt++) {
                int col = n0 + wn * 32 + nt * 8 + 2 * th4;
#pragma unroll
                for (int h = 0; h < 2; h++) {
                    int row = m0 + wm * 64 + mt * 16 + g + 8 * h;
                    float e0 = __expf(acc[mt][nt][2 * h]);
                    float e1 = __expf(acc[mt][nt][2 * h + 1]);
                    rsum[mt * 2 + h] += e0 + e1;
                    *(__half2*)(C + (size_t)row * ldC + col) = __floats2half2_rn(e0, e1);
                }
            }
        }
#pragma unroll
        for (int i = 0; i < 8; i++) {
            rsum[i] += __shfl_xor_sync(0xffffffffu, rsum[i], 1);
            rsum[i] += __shfl_xor_sync(0xffffffffu, rsum[i], 2);
        }
        if (th4 == 0) {
#pragma unroll
            for (int mt = 0; mt < 4; mt++)
#pragma unroll
                for (int h = 0; h < 2; h++)
                    cs[wn * 128 + wm * 64 + mt * 16 + g + 8 * h] = rsum[mt * 2 + h];
        }
        __syncthreads();
        if (tid < 128) {
            float tot = cs[tid] + cs[128 + tid] + cs[256 + tid] + cs[384 + tid];
            psum[((size_t)b * NMT + blockIdx.x) * M + m0 + tid] = tot;
        }
        return;
    }

    if (mode == 3) {
        float* C = (float*)Cv + (size_t)b * sC;
        const float* R = residual + (size_t)b * sC;
#pragma unroll
        for (int mt = 0; mt < 4; mt++) {
#pragma unroll
            for (int nt = 0; nt < 4; nt++) {
                int col = n0 + wn * 32 + nt * 8 + 2 * th4;
#pragma unroll
                for (int h = 0; h < 2; h++) {
                    int row = m0 + wm * 64 + mt * 16 + g + 8 * h;
                    float br = bias_row[row];
                    float2 rv = *(const float2*)(R + (size_t)row * ldC + col);
                    float2 o;
                    o.x = acc[mt][nt][2 * h]     + br + rv.x;
                    o.y = acc[mt][nt][2 * h + 1] + br + rv.y;
                    *(float2*)(C + (size_t)row * ldC + col) = o;
                }
            }
        }
        return;
    }

    __half* C = (__half*)Cv + (size_t)b * sC;
    const float* rsc = (mode == 2) ? (rowscale + (size_t)b * M) : nullptr;
#pragma unroll
    for (int mt = 0; mt < 4; mt++) {
#pragma unroll
        for (int nt = 0; nt < 4; nt++) {
            int col = n0 + wn * 32 + nt * 8 + 2 * th4;
            float bc0 = bias_col ? bias_col[col]     : 0.f;
            float bc1 = bias_col ? bias_col[col + 1] : 0.f;
#pragma unroll
            for (int h = 0; h < 2; h++) {
                int row = m0 + wm * 64 + mt * 16 + g + 8 * h;
                float o0 = acc[mt][nt][2 * h];
                float o1 = acc[mt][nt][2 * h + 1];
                if (mode == 2) {
                    float sc = rsc[row];
                    o0 *= sc; o1 *= sc;
                } else {
                    o0 += bc0; o1 += bc1;
                }
                *(__half2*)(C + (size_t)row * ldC + col) = __floats2half2_rn(o0, o1);
            }
        }
    }
}

// ---------------- invL: reduce partial row sums ------------------------------
__global__ void invl_reduce()
{
    int idx = blockIdx.x * blockDim.x + threadIdx.x;   // b*NN + nq
    int b = idx >> 12;
    int n = idx & (NN - 1);
    float s = 0.f;
#pragma unroll
    for (int t = 0; t < NMT; t++)
        s += g_ps[((size_t)b * NMT + t) * NN + n];
    g_invL[idx] = 1.f / s;
}

// ---------------- launch -----------------------------------------------------
extern "C" void kernel_launch(void* const* d_in, const int* in_sizes, int n_in,
                              void* d_out, int out_size)
{
    const float* x     = (const float*)d_in[0];
    const float* gamma = (const float*)d_in[1];
    const float* beta  = (const float*)d_in[2];
    const float* wq    = (const float*)d_in[3];
    const float* bq    = (const float*)d_in[4];
    const float* wk    = (const float*)d_in[5];
    const float* bk    = (const float*)d_in[6];
    const float* wv    = (const float*)d_in[7];
    const float* bv    = (const float*)d_in[8];
    const float* wo    = (const float*)d_in[9];
    const float* bo    = (const float*)d_in[10];
    float* out = (float*)d_out;

    __half *wqkvh, *woh, *hn, *qkv, *eS, *at;
    float *bqkv, *ps, *invL;
    cudaGetSymbolAddress((void**)&wqkvh, g_wqkvh);
    cudaGetSymbolAddress((void**)&woh,   g_woh);
    cudaGetSymbolAddress((void**)&bqkv,  g_bqkv);
    cudaGetSymbolAddress((void**)&hn,    g_hn);
    cudaGetSymbolAddress((void**)&qkv,   g_qkv);
    cudaGetSymbolAddress((void**)&eS,    g_eS);
    cudaGetSymbolAddress((void**)&at,    g_at);
    cudaGetSymbolAddress((void**)&ps,    g_ps);
    cudaGetSymbolAddress((void**)&invL,  g_invL);

    constexpr int SMEM0 = STAGES * (TILE_A + TILE_B0);
    constexpr int SMEM1 = STAGES * (TILE_A + TILE_B1);

    static bool attr_set = false;
    if (!attr_set) {
        cudaFuncSetAttribute(hgemm<0>, cudaFuncAttributeMaxDynamicSharedMemorySize, SMEM0);
        cudaFuncSetAttribute(hgemm<1>, cudaFuncAttributeMaxDynamicSharedMemorySize, SMEM1);
        attr_set = true;
    }

    prep_weights<<<(262912 + 255) / 256, 256>>>(wq, wk, wv, wo, bq, bk, bv);
    gn_stats<<<BB * GG, 256>>>(x);
    gn_transpose<<<dim3(NN / 32, CC / 32, BB), dim3(32, 8)>>>(x, gamma, beta);

    // qkv[n][768] = hn[n][c] x wqkv[d][c]^T + bqkv   (grid 6x32x4)
    hgemm<0><<<dim3(768 / TBN, NN / TBM, BB), 256, SMEM0>>>(
        hn, CC, (size_t)NN * CC, wqkvh, CC, 0,
        qkv, 768, (size_t)NN * 768, NN, CC,
        nullptr, bqkv, nullptr, nullptr, nullptr, 0);

    // expS[nq][nk] = exp(q . k), per-block row sums   (grid 32x32x4)
    hgemm<0><<<dim3(NN / TBN, NN / TBM, BB), 256, SMEM0>>>(
        qkv, 768, (size_t)NN * 768, qkv + 256, 768, (size_t)NN * 768,
        eS, NN, (size_t)NN * NN, NN, CC,
        nullptr, nullptr, nullptr, nullptr, ps, 1);

    invl_reduce<<<BB * NN / 256, 256>>>();

    // attn[nq][c] = (expS[nq][nk] x v[nk][c]) * invL[nq]   (BTRANS, grid 2x32x4)
    hgemm<1><<<dim3(CC / TBN, NN / TBM, BB), 256, SMEM1>>>(
        eS, NN, (size_t)NN * NN, qkv + 512, 768, (size_t)NN * 768,
        at, CC, (size_t)NN * CC, NN, NN,
        nullptr, nullptr, nullptr, invL, nullptr, 2);

    // out[c][n] = wo[c][k] x attn[n][k]^T + bo[c] + x[c][n]   (fp32, grid 32x2x4)
    hgemm<0><<<dim3(NN / TBN, CC / TBM, BB), 256, SMEM0>>>(
        woh, CC, 0, at, CC, (size_t)NN * CC,
        out, NN, (size_t)CC * NN, CC, CC,
        bo, nullptr, x, nullptr, nullptr, 3);
}